// round 7
// baseline (speedup 1.0000x reference)
#include <cuda_runtime.h>

// PartialSum: out[b, p] = sum over 64 contiguous floats of x[b, p*64 : (p+1)*64]
// x: [2048, 65536] f32  -> out: [2048, 1024] f32 (2,097,152 partitions)
//
// Persistent grid-stride version of the R4 tile: one wave of 1184 CTAs
// (148 SMs x 8 CTAs), each looping over tiles. Eliminates wave-transition /
// CTA launch-drain gaps; loop keeps 4 coalesced LDG.128s in flight
// continuously (next tile's loads overlap current tile's shuffle tail).

__global__ void __launch_bounds__(256) partial_sum_kernel(
    const float4* __restrict__ x4, float* __restrict__ out, int n_tiles)
{
    int t = threadIdx.x;
    int lane_grp = t >> 4;           // which of 16 partitions this tile
    bool writer = (t & 15) == 0;

    for (int tile = blockIdx.x; tile < n_tiles; tile += gridDim.x) {
        int base = tile * 1024 + t;                // float4 index of load 0

        float4 a = __ldcs(&x4[base]);
        float4 b = __ldcs(&x4[base + 256]);
        float4 c = __ldcs(&x4[base + 512]);
        float4 d = __ldcs(&x4[base + 768]);

        float sa = (a.x + a.y) + (a.z + a.w);
        float sb = (b.x + b.y) + (b.z + b.w);
        float sc = (c.x + c.y) + (c.z + c.w);
        float sd = (d.x + d.y) + (d.z + d.w);

        #pragma unroll
        for (int off = 8; off > 0; off >>= 1) {
            sa += __shfl_down_sync(0xffffffffu, sa, off, 16);
            sb += __shfl_down_sync(0xffffffffu, sb, off, 16);
            sc += __shfl_down_sync(0xffffffffu, sc, off, 16);
            sd += __shfl_down_sync(0xffffffffu, sd, off, 16);
        }

        if (writer) {
            int p = tile * 64 + lane_grp;          // partition of load 0
            out[p]      = sa;
            out[p + 16] = sb;
            out[p + 32] = sc;
            out[p + 48] = sd;
        }
    }
}

extern "C" void kernel_launch(void* const* d_in, const int* in_sizes, int n_in,
                              void* d_out, int out_size)
{
    const float4* x4 = (const float4*)d_in[0];
    float* out = (float*)d_out;

    int n_tiles = out_size / 64;                   // 32768 tiles of 64 partitions
    int blocks = 148 * 8;                          // one full wave, persistent
    if (blocks > n_tiles) blocks = n_tiles;

    partial_sum_kernel<<<blocks, 256>>>(x4, out, n_tiles);
}

// round 8
// speedup vs baseline: 1.0687x; 1.0687x over previous
#include <cuda_runtime.h>

// PartialSum: out[b, p] = sum over 64 contiguous floats of x[b, p*64 : (p+1)*64]
// x: [2048, 65536] f32  -> out: [2048, 1024] f32 (2,097,152 partitions)
//
// R4 structure (proven 80.4us / 86% DRAM): 4 independent, individually
// warp-coalesced LDG.128 per thread (MLP_p1=4), 16 lanes per partition,
// 4 independent shfl_down trees, writer lane stores 4 outputs.
// This round: 512-thread blocks (128 partitions / 2048 float4 per block,
// 16384 blocks) to shave CTA ramp/transition overhead. Everything else
// identical to the best kernel.

__global__ void __launch_bounds__(512) partial_sum_kernel(
    const float4* __restrict__ x4, float* __restrict__ out)
{
    int t = threadIdx.x;
    int base = blockIdx.x * 2048 + t;              // float4 index of load 0

    // 4 independent, individually warp-coalesced loads (front-batched, MLP=4)
    float4 a = __ldg(&x4[base]);
    float4 b = __ldg(&x4[base + 512]);
    float4 c = __ldg(&x4[base + 1024]);
    float4 d = __ldg(&x4[base + 1536]);

    float sa = (a.x + a.y) + (a.z + a.w);
    float sb = (b.x + b.y) + (b.z + b.w);
    float sc = (c.x + c.y) + (c.z + c.w);
    float sd = (d.x + d.y) + (d.z + d.w);

    // 4 independent 16-lane reduction trees (interleaved for ILP).
    #pragma unroll
    for (int off = 8; off > 0; off >>= 1) {
        sa += __shfl_down_sync(0xffffffffu, sa, off, 16);
        sb += __shfl_down_sync(0xffffffffu, sb, off, 16);
        sc += __shfl_down_sync(0xffffffffu, sc, off, 16);
        sd += __shfl_down_sync(0xffffffffu, sd, off, 16);
    }

    if ((t & 15) == 0) {
        int p = blockIdx.x * 128 + (t >> 4);       // partition of load 0
        out[p]      = sa;   // loads 1..3 are +32/+64/+96 partitions away
        out[p + 32] = sb;
        out[p + 64] = sc;
        out[p + 96] = sd;
    }
}

extern "C" void kernel_launch(void* const* d_in, const int* in_sizes, int n_in,
                              void* d_out, int out_size)
{
    const float4* x4 = (const float4*)d_in[0];
    float* out = (float*)d_out;

    int blocks = out_size / 128;                   // 2,097,152 / 128 = 16384
    partial_sum_kernel<<<blocks, 512>>>(x4, out);
}